// round 10
// baseline (speedup 1.0000x reference)
#include <cuda_runtime.h>
#include <math.h>

#define NNODES 512
#define IND    768
#define HIDD   64
#define NHEAD  4
#define HD1    256
#define KCC    192
#define OUTDIM 256
#define NT     768
#define NG     3
#define GSZ    256
#define SMG    7680         // smem floats per warpgroup
#define RS     20           // smem row stride (16 k + 4 pad)

// ----------------------------------------------------------------------------
// Device scratch
// ----------------------------------------------------------------------------
__device__ float g_z1[NNODES * HD1];
__device__ float g_h1[NNODES * HD1];
__device__ float g_z2[NNODES * IND];
__device__ float g_h2[NNODES * IND];
__device__ float g_r [NNODES * KCC];
__device__ float g_part[8 * NNODES * IND];
__device__ float g_ssrc[NHEAD * NNODES], g_sdst[NHEAD * NNODES];
__device__ float g_Af[NHEAD * NNODES], g_Cf[NHEAD * NNODES];
__device__ float g_Bp[NHEAD * NNODES], g_Dp[NHEAD * NNODES];
__device__ float g_mxc[IND], g_invc[IND];
__device__ float g_rsum[KCC];
__device__ unsigned g_cnt8[8];
__device__ unsigned g_root = 0;
__device__ volatile unsigned g_bargen = 0;

// ----------------------------------------------------------------------------
// Barriers + cp.async helpers
// ----------------------------------------------------------------------------
__device__ __forceinline__ void wgsync(int wg) {
    asm volatile("bar.sync %0, %1;" :: "r"(wg + 1), "n"(GSZ) : "memory");
}

__device__ __forceinline__ void gridbar() {
    __syncthreads();
    if (threadIdx.x == 0) {
        __threadfence();
        const unsigned gen = g_bargen;
        const unsigned b = blockIdx.x & 7u;
        const unsigned bsz = (gridDim.x >> 3) + (((gridDim.x & 7u) > b) ? 1u : 0u);
        if (atomicAdd(&g_cnt8[b], 1u) == bsz - 1u) {
            atomicExch(&g_cnt8[b], 0u);
            __threadfence();
            if (atomicAdd(&g_root, 1u) == 7u) {
                atomicExch(&g_root, 0u);
                __threadfence();
                atomicAdd((unsigned*)&g_bargen, 1u);
            }
        }
        while (g_bargen == gen) { __nanosleep(32); }
        __threadfence();
    }
    __syncthreads();
}

__device__ __forceinline__ unsigned su32(const void* p) {
    return (unsigned)__cvta_generic_to_shared(p);
}
__device__ __forceinline__ void cpa16(unsigned d, const void* s) {
    asm volatile("cp.async.cg.shared.global [%0], [%1], 16;" :: "r"(d), "l"(s));
}
__device__ __forceinline__ void cpcommit() { asm volatile("cp.async.commit_group;"); }
__device__ __forceinline__ void cpwait0()  { asm volatile("cp.async.wait_group 0;"); }

// ----------------------------------------------------------------------------
// 128x64-tile pipelined SGEMM, 8x4/thread, chunk=16, one barrier per chunk.
// Cpart[z][M,Ncols] = A[M,K_ld] @ B[Ncols,K_ld]^T over k-split z. M tiles of 128.
// smem: As[2][128][RS], Bs[2][64][RS].
// ----------------------------------------------------------------------------
__device__ void ph_gemm_abt128(const float* __restrict__ A, const float* __restrict__ B,
                               float* __restrict__ C, int Ncols, int K_ld, int klen,
                               int gx, int gy, int nsplit,
                               int ltid, int wg, int grp, int ngrp, float* gsm)
{
    float* As = gsm;                 // 2 * 2560
    float* Bs = gsm + 5120;          // 2 * 1280
    const int tx = ltid & 15, ty = ltid >> 4;
    const int arow = ltid >> 1, ah = (ltid & 1) * 8;    // A staging: 2 thr/row
    const int brow = ltid >> 2, bq = (ltid & 3) * 4;    // B staging: 4 thr/row
    const int njobs = gx * gy * nsplit;
    const int nch = klen >> 4;

    for (int job = grp; job < njobs; job += ngrp) {
        const int z = job / (gx * gy);
        const int rem = job % (gx * gy);
        const int by = rem / gx, bx = rem % gx;
        const int m0 = by * 128, n0 = bx * 64, kstart = z * klen;

        const float* srcA = A + (size_t)(m0 + arow) * K_ld + kstart + ah;
        const float* srcB = B + (size_t)(n0 + brow) * K_ld + kstart + bq;
        const unsigned dstA = su32(&As[arow * RS + ah]);
        const unsigned dstB = su32(&Bs[brow * RS + bq]);

        float acc[8][4];
#pragma unroll
        for (int i = 0; i < 8; i++)
#pragma unroll
            for (int j = 0; j < 4; j++) acc[i][j] = 0.f;

        wgsync(wg);
        cpa16(dstA, srcA);
        cpa16(dstA + 16, srcA + 4);
        cpa16(dstB, srcB);
        cpcommit();

        for (int c = 0; c < nch; c++) {
            const int cb = c & 1;
            cpwait0();
            wgsync(wg);
            if (c + 1 < nch) {
                const unsigned dA = dstA + (cb ^ 1) * 10240;   // 2560 floats
                const unsigned dB = dstB + (cb ^ 1) * 5120;    // 1280 floats
                const float* sA = srcA + (c + 1) * 16;
                const float* sB = srcB + (c + 1) * 16;
                cpa16(dA, sA);
                cpa16(dA + 16, sA + 4);
                cpa16(dB, sB);
                cpcommit();
            }
            const float* Ab = As + cb * 2560;
            const float* Bb = Bs + cb * 1280;
#pragma unroll
            for (int q = 0; q < 4; q++) {
                float4 af[8], bf[4];
#pragma unroll
                for (int i = 0; i < 8; i++)
                    af[i] = *(const float4*)&Ab[(ty + 16 * i) * RS + q * 4];
#pragma unroll
                for (int j = 0; j < 4; j++)
                    bf[j] = *(const float4*)&Bb[(tx + 16 * j) * RS + q * 4];
#pragma unroll
                for (int i = 0; i < 8; i++)
#pragma unroll
                    for (int j = 0; j < 4; j++) {
                        acc[i][j] += af[i].x * bf[j].x;
                        acc[i][j] += af[i].y * bf[j].y;
                        acc[i][j] += af[i].z * bf[j].z;
                        acc[i][j] += af[i].w * bf[j].w;
                    }
            }
        }

        float* outp = C + (size_t)z * NNODES * Ncols;
#pragma unroll
        for (int i = 0; i < 8; i++)
#pragma unroll
            for (int j = 0; j < 4; j++)
                outp[(size_t)(m0 + ty + 16 * i) * Ncols + n0 + tx + 16 * j] = acc[i][j];
    }
}

// ----------------------------------------------------------------------------
// 128x64-tile aggregation GEMM (for layer2 agg), 8x4/thread, chunk=16.
// alpha[j][i] = (i!=j)*sel(ss[i]+d[j]>0, Af[i]*Bp[j], Cf[i]*Dp[j]) in smem.
// smem: Asb[2][16][132], Zs[2][16][68], Ex[384]. j = m0 + ty*8 + u? NO:
// j mapping: frag a = Asb[kk][ty*8 .. ty*8+7]; output row m0 + ty*8 + u.
// ----------------------------------------------------------------------------
__device__ void ph_gemm_agg128(const float* __restrict__ Z, float* __restrict__ C,
                               const float* __restrict__ ssrc, const float* __restrict__ sdst,
                               const float* __restrict__ Af, const float* __restrict__ Cf,
                               const float* __restrict__ Bp, const float* __restrict__ Dp,
                               int ldz, int gx, int gy, int nsplit,
                               int klen, int ldc,
                               int ltid, int wg, int grp, int ngrp, float* gsm)
{
    float* Asb = gsm;              // 2 * 2112 (16 x 132)
    float* Zs  = gsm + 4224;       // 2 * 1088 (16 x 68)
    float* Ex  = gsm + 6400;       // 384
    const int tx = ltid & 15, ty = ltid >> 4;
    const int zrow = ltid >> 4, zf4 = ltid & 15;
    const int ail = ltid >> 4;              // k within chunk (0-15)
    const int aj8 = (ltid & 15) * 8;        // j group of 8
    const int njobs = gx * gy * nsplit;
    const int nch = klen >> 4;

    for (int job = grp; job < njobs; job += ngrp) {
        const int z = job / (gx * gy);
        const int rem = job % (gx * gy);
        const int by = rem / gx, bx = rem % gx;
        const int m0 = by * 128, ncol0 = bx * 64, kstart = z * klen;

        auto build = [&](int cc, float* dst) {
            int ig = kstart + cc * 16 + ail;
            float ssv = ssrc[ig], afv = Af[ig], cfv = Cf[ig];
#pragma unroll
            for (int half = 0; half < 2; half++) {
                int jj = aj8 + half * 4;
                float4 w;
                float x0 = ssv + Ex[jj + 0];
                float x1 = ssv + Ex[jj + 1];
                float x2 = ssv + Ex[jj + 2];
                float x3 = ssv + Ex[jj + 3];
                w.x = x0 > 0.f ? afv * Ex[128 + jj + 0] : cfv * Ex[256 + jj + 0];
                w.y = x1 > 0.f ? afv * Ex[128 + jj + 1] : cfv * Ex[256 + jj + 1];
                w.z = x2 > 0.f ? afv * Ex[128 + jj + 2] : cfv * Ex[256 + jj + 2];
                w.w = x3 > 0.f ? afv * Ex[128 + jj + 3] : cfv * Ex[256 + jj + 3];
                if (ig == m0 + jj + 0) w.x = 0.f;
                if (ig == m0 + jj + 1) w.y = 0.f;
                if (ig == m0 + jj + 2) w.z = 0.f;
                if (ig == m0 + jj + 3) w.w = 0.f;
                *(float4*)&dst[ail * 132 + jj] = w;
            }
        };

        wgsync(wg);
        if (ltid < 128) {
            int j = m0 + ltid;
            Ex[ltid]       = sdst[j];
            Ex[128 + ltid] = Bp[j];
            Ex[256 + ltid] = Dp[j];
        }
        wgsync(wg);                         // Ex visible before build

        build(0, Asb);
        const float* srcZ = Z + (size_t)(kstart + zrow) * ldz + ncol0 + zf4 * 4;
        const unsigned dstZ = su32(&Zs[zrow * 68 + zf4 * 4]);
        cpa16(dstZ, srcZ);
        cpcommit();

        float acc[8][4];
#pragma unroll
        for (int i = 0; i < 8; i++)
#pragma unroll
            for (int j = 0; j < 4; j++) acc[i][j] = 0.f;

        for (int c = 0; c < nch; c++) {
            const int cb = c & 1;
            cpwait0();
            wgsync(wg);
            if (c + 1 < nch) {
                cpa16(dstZ + (cb ^ 1) * 4352, srcZ + (size_t)(c + 1) * 16 * ldz);
                cpcommit();
                build(c + 1, Asb + (cb ^ 1) * 2112);
            }
            const float* Ab = Asb + cb * 2112;
            const float* Zb = Zs  + cb * 1088;
#pragma unroll
            for (int kk = 0; kk < 16; kk++) {
                float4 a0 = *(const float4*)&Ab[kk * 132 + ty * 8];
                float4 a1 = *(const float4*)&Ab[kk * 132 + ty * 8 + 4];
                float4 b  = *(const float4*)&Zb[kk * 68 + tx * 4];
                float a8[8] = {a0.x, a0.y, a0.z, a0.w, a1.x, a1.y, a1.z, a1.w};
                float b4[4] = {b.x, b.y, b.z, b.w};
#pragma unroll
                for (int i = 0; i < 8; i++)
#pragma unroll
                    for (int j = 0; j < 4; j++) acc[i][j] += a8[i] * b4[j];
            }
        }

        float* outp = C + (size_t)z * NNODES * ldc;
#pragma unroll
        for (int i = 0; i < 8; i++)
#pragma unroll
            for (int j = 0; j < 4; j++)
                outp[(size_t)(m0 + ty * 8 + i) * ldc + ncol0 + tx * 4 + j] = acc[i][j];
    }
}

// ----------------------------------------------------------------------------
// 64x64 aggregation GEMM (layer1 heads), 4x4/thread (as R9)
// ----------------------------------------------------------------------------
__device__ void ph_gemm_agg64(const float* __restrict__ Z, float* __restrict__ C,
                              const float* __restrict__ ssrc, const float* __restrict__ sdst,
                              const float* __restrict__ Af, const float* __restrict__ Cf,
                              const float* __restrict__ Bp, const float* __restrict__ Dp,
                              int ldz, int hd, int gx, int gy, int nsplit, int H,
                              int klen, int ldc,
                              int ltid, int wg, int grp, int ngrp, float* gsm)
{
    float* Asb = gsm;              // 2 * 1088
    float* Zs  = gsm + 2176;       // 2 * 1088
    float* Ex  = gsm + 4352;       // 192
    const int tx = ltid & 15, ty = ltid >> 4;
    const int zrow = ltid >> 4, zf4 = ltid & 15;
    const int ail = ltid >> 4, aj4 = (ltid & 15) * 4;
    const int jobs_per_h = gx * gy * nsplit;
    const int njobs = H * jobs_per_h;
    const int nch = klen >> 4;

    for (int job = grp; job < njobs; job += ngrp) {
        const int h = job / jobs_per_h;
        int rem = job % jobs_per_h;
        const int z = rem / (gx * gy); rem %= gx * gy;
        const int by = rem / gx, bx = rem % gx;
        const int m0 = by * 64, ncol0 = h * hd + bx * 64, kstart = z * klen;
        const float* ss = ssrc + h * NNODES;
        const float* af = Af + h * NNODES;
        const float* cf = Cf + h * NNODES;

        auto build = [&](int cc, float* dst) {
            int ig = kstart + cc * 16 + ail;
            float ssv = ss[ig], afv = af[ig], cfv = cf[ig];
            int jj = aj4;
            float4 w;
            float x0 = ssv + Ex[jj + 0];
            float x1 = ssv + Ex[jj + 1];
            float x2 = ssv + Ex[jj + 2];
            float x3 = ssv + Ex[jj + 3];
            w.x = x0 > 0.f ? afv * Ex[64 + jj + 0] : cfv * Ex[128 + jj + 0];
            w.y = x1 > 0.f ? afv * Ex[64 + jj + 1] : cfv * Ex[128 + jj + 1];
            w.z = x2 > 0.f ? afv * Ex[64 + jj + 2] : cfv * Ex[128 + jj + 2];
            w.w = x3 > 0.f ? afv * Ex[64 + jj + 3] : cfv * Ex[128 + jj + 3];
            if (ig == m0 + jj + 0) w.x = 0.f;
            if (ig == m0 + jj + 1) w.y = 0.f;
            if (ig == m0 + jj + 2) w.z = 0.f;
            if (ig == m0 + jj + 3) w.w = 0.f;
            *(float4*)&dst[ail * 68 + aj4] = w;
        };

        wgsync(wg);
        if (ltid < 64) {
            int j = m0 + ltid;
            Ex[ltid]       = sdst[h * NNODES + j];
            Ex[64 + ltid]  = Bp[h * NNODES + j];
            Ex[128 + ltid] = Dp[h * NNODES + j];
        }
        wgsync(wg);

        build(0, Asb);
        const float* srcZ = Z + (size_t)(kstart + zrow) * ldz + ncol0 + zf4 * 4;
        const unsigned dstZ = su32(&Zs[zrow * 68 + zf4 * 4]);
        cpa16(dstZ, srcZ);
        cpcommit();

        float acc[4][4];
#pragma unroll
        for (int i = 0; i < 4; i++)
#pragma unroll
            for (int j = 0; j < 4; j++) acc[i][j] = 0.f;

        for (int c = 0; c < nch; c++) {
            const int cb = c & 1;
            cpwait0();
            wgsync(wg);
            if (c + 1 < nch) {
                cpa16(dstZ + (cb ^ 1) * 4352, srcZ + (size_t)(c + 1) * 16 * ldz);
                cpcommit();
                build(c + 1, Asb + (cb ^ 1) * 1088);
            }
            const float* Ab = Asb + cb * 1088;
            const float* Zb = Zs  + cb * 1088;
#pragma unroll
            for (int kk = 0; kk < 16; kk++) {
                float4 a = *(const float4*)&Ab[kk * 68 + ty * 4];
                float4 b = *(const float4*)&Zb[kk * 68 + tx * 4];
                float a4[4] = {a.x, a.y, a.z, a.w};
                float b4[4] = {b.x, b.y, b.z, b.w};
#pragma unroll
                for (int i = 0; i < 4; i++)
#pragma unroll
                    for (int j = 0; j < 4; j++) acc[i][j] += a4[i] * b4[j];
            }
        }

        float* outp = C + (size_t)z * NNODES * ldc;
#pragma unroll
        for (int i = 0; i < 4; i++)
#pragma unroll
            for (int j = 0; j < 4; j++)
                outp[(size_t)(m0 + ty * 4 + i) * ldc + ncol0 + tx * 4 + j] = acc[i][j];
    }
}

// ----------------------------------------------------------------------------
// fc1 GEMM 64x64 with softmax folded into A build (as R9)
// ----------------------------------------------------------------------------
__device__ void ph_gemm_fc1(const float* __restrict__ h2m, const float* __restrict__ mxc,
                            const float* __restrict__ invc, const float* __restrict__ Bw,
                            float* __restrict__ C,
                            int ltid, int wg, int grp, int ngrp, float* gsm)
{
    float* As = gsm;
    float* Bs = gsm + 2560;
    const int tx = ltid & 15, ty = ltid >> 4;
    const int row = ltid >> 2, kq = (ltid & 3) * 4;
    const int njobs = 384;
    const int nch = 3;

    for (int job = grp; job < njobs; job += ngrp) {
        const int z = job / 24;
        const int rem = job % 24;
        const int by = rem / 3, bx = rem % 3;
        const int m0 = by * 64, n0 = bx * 64, kstart = z * 48;

        const unsigned dstB = su32(&Bs[row * RS + kq]);
        const float* srcB = Bw + (size_t)(n0 + row) * IND + kstart + kq;
        const float* srcA = h2m + (size_t)(m0 + row) * IND + kstart + kq;

        float acc[4][4];
#pragma unroll
        for (int i = 0; i < 4; i++)
#pragma unroll
            for (int j = 0; j < 4; j++) acc[i][j] = 0.f;

        wgsync(wg);
        cpa16(dstB, srcB);
        cpcommit();
        {
            float4 raw = *(const float4*)srcA;
            float4 mx  = *(const float4*)&mxc[kstart + kq];
            float4 iv  = *(const float4*)&invc[kstart + kq];
            float4 v;
            v.x = __expf(raw.x - mx.x) * iv.x;
            v.y = __expf(raw.y - mx.y) * iv.y;
            v.z = __expf(raw.z - mx.z) * iv.z;
            v.w = __expf(raw.w - mx.w) * iv.w;
            *(float4*)&As[row * RS + kq] = v;
        }

        for (int c = 0; c < nch; c++) {
            const int cb = c & 1;
            cpwait0();
            wgsync(wg);
            float4 raw;
            const bool pre = (c + 1 < nch);
            if (pre) {
                cpa16(dstB + (cb ^ 1) * 5120u, srcB + (c + 1) * 16);
                cpcommit();
                raw = *(const float4*)(srcA + (c + 1) * 16);
            }
            const float* Ab = As + cb * 1280;
            const float* Bb = Bs + cb * 1280;
#pragma unroll
            for (int q = 0; q < 4; q++) {
                float4 af[4], bf[4];
#pragma unroll
                for (int i = 0; i < 4; i++)
                    af[i] = *(const float4*)&Ab[(ty + 16 * i) * RS + q * 4];
#pragma unroll
                for (int j = 0; j < 4; j++)
                    bf[j] = *(const float4*)&Bb[(tx + 16 * j) * RS + q * 4];
#pragma unroll
                for (int i = 0; i < 4; i++)
#pragma unroll
                    for (int j = 0; j < 4; j++) {
                        acc[i][j] += af[i].x * bf[j].x;
                        acc[i][j] += af[i].y * bf[j].y;
                        acc[i][j] += af[i].z * bf[j].z;
                        acc[i][j] += af[i].w * bf[j].w;
                    }
            }
            if (pre) {
                const int kg = kstart + (c + 1) * 16 + kq;
                float4 mx = *(const float4*)&mxc[kg];
                float4 iv = *(const float4*)&invc[kg];
                float4 v;
                v.x = __expf(raw.x - mx.x) * iv.x;
                v.y = __expf(raw.y - mx.y) * iv.y;
                v.z = __expf(raw.z - mx.z) * iv.z;
                v.w = __expf(raw.w - mx.w) * iv.w;
                *(float4*)&As[(cb ^ 1) * 1280 + row * RS + kq] = v;
            }
        }

        float* outp = C + (size_t)z * NNODES * KCC;
#pragma unroll
        for (int i = 0; i < 4; i++)
#pragma unroll
            for (int j = 0; j < 4; j++)
                outp[(size_t)(m0 + ty + 16 * i) * KCC + n0 + tx + 16 * j] = acc[i][j];
    }
}

// ----------------------------------------------------------------------------
// Elementwise / reduction phases
// ----------------------------------------------------------------------------
__device__ void ph_combine(float* __restrict__ out, const float* __restrict__ part,
                           int nparts, int total, int ncols,
                           const float* __restrict__ bias, int act)
{
    for (int idx = blockIdx.x * NT + threadIdx.x; idx < total; idx += gridDim.x * NT) {
        float s = 0.f;
        for (int p = 0; p < nparts; p++) s += part[(size_t)p * total + idx];
        if (bias) s += bias[idx % ncols];
        if (act == 1) s = fmaxf(s, 0.f);
        else if (act == 2) s = s > 0.f ? s : expm1f(s);
        out[idx] = s;
    }
}

__device__ void ph_scores(const float* __restrict__ z, int ldz,
                          const float* __restrict__ a, int D,
                          float* __restrict__ ssrc, float* __restrict__ sdst, int H)
{
    const int lane = threadIdx.x & 31;
    const int gw = blockIdx.x * (NT / 32) + (threadIdx.x >> 5);
    const int nw = gridDim.x * (NT / 32);
    for (int w = gw; w < H * NNODES; w += nw) {
        int h = w / NNODES, i = w % NNODES;
        const float* zr = z + (size_t)i * ldz + h * D;
        const float* ar = a + (size_t)h * 2 * D;
        float s1 = 0.f, s2 = 0.f;
        for (int d = lane; d < D; d += 32) {
            float v = zr[d];
            s1 += v * ar[d];
            s2 += v * ar[D + d];
        }
#pragma unroll
        for (int o = 16; o; o >>= 1) {
            s1 += __shfl_xor_sync(0xffffffffu, s1, o);
            s2 += __shfl_xor_sync(0xffffffffu, s2, o);
        }
        if (lane == 0) { ssrc[h * NNODES + i] = s1; sdst[h * NNODES + i] = s2; }
    }
}

__device__ void ph_stats(const float* __restrict__ ssrc, const float* __restrict__ sdst,
                         float* __restrict__ Af, float* __restrict__ Cf,
                         float* __restrict__ Bpg, float* __restrict__ Dpg,
                         int H, int ltid, int wg, int grp, int ngrp, float* gsm)
{
    float* ss  = gsm;
    float* aa  = gsm + 512;
    float* cc  = gsm + 1024;
    float* rm1 = gsm + 1536;
    float* rm2 = gsm + 1792;
    int*   ri1 = (int*)(gsm + 2048);
    const int cpj = NNODES / 64;
    const int njobs = H * cpj;

    for (int job = grp; job < njobs; job += ngrp) {
        const int h = job / cpj, jc = job % cpj;
        wgsync(wg);
        for (int i = ltid; i < NNODES; i += GSZ) ss[i] = ssrc[h * NNODES + i];
        wgsync(wg);

        float m1 = -1e30f, m2 = -1e30f; int i1 = -1;
        for (int i = ltid; i < NNODES; i += GSZ) {
            float v = ss[i];
            if (v > m1) { m2 = m1; m1 = v; i1 = i; }
            else if (v > m2) m2 = v;
        }
        rm1[ltid] = m1; rm2[ltid] = m2; ri1[ltid] = i1;
        wgsync(wg);
        if (ltid < 32) {
            float a1 = rm1[ltid], a2 = rm2[ltid]; int ai = ri1[ltid];
            for (int t = ltid + 32; t < GSZ; t += 32) {
                float b1 = rm1[t], b2 = rm2[t];
                if (b1 > a1) { a2 = fmaxf(a1, b2); a1 = b1; ai = ri1[t]; }
                else         { a2 = fmaxf(a2, b1); }
            }
            rm1[ltid] = a1; rm2[ltid] = a2; ri1[ltid] = ai;
        }
        wgsync(wg);
        if (ltid == 0) {
            float a1 = rm1[0], a2 = rm2[0]; int ai = ri1[0];
            for (int t = 1; t < 32; t++) {
                float b1 = rm1[t], b2 = rm2[t];
                if (b1 > a1) { a2 = fmaxf(a1, b2); a1 = b1; ai = ri1[t]; }
                else         { a2 = fmaxf(a2, b1); }
            }
            rm1[0] = a1; rm2[0] = a2; ri1[0] = ai;
        }
        wgsync(wg);
        const float Ms = rm1[0], M2 = rm2[0];
        const int iarg = ri1[0];

        for (int i = ltid; i < NNODES; i += GSZ) {
            float d = ss[i] - Ms;
            aa[i] = __expf(d);
            cc[i] = __expf(0.01f * d);
        }
        wgsync(wg);
        if (jc == 0) {
            for (int i = ltid; i < NNODES; i += GSZ) {
                Af[h * NNODES + i] = aa[i];
                Cf[h * NNODES + i] = cc[i];
            }
        }

        const int wid = ltid >> 5, lane = ltid & 31;
        for (int jj = wid; jj < 64; jj += 8) {
            int j = jc * 64 + jj;
            float sd = sdst[h * NNODES + j];
            float smx = (j == iarg) ? M2 : Ms;
            float t0 = smx + sd;
            float mxj = t0 > 0.f ? t0 : 0.01f * t0;
            float Bj = __expf(Ms + sd - mxj);
            float Dj = __expf(0.01f * (Ms + sd) - mxj);
            float ssum = 0.f;
            for (int i = lane; i < NNODES; i += 32) {
                if (i == j) continue;
                float x = ss[i] + sd;
                ssum += (x > 0.f) ? aa[i] * Bj : cc[i] * Dj;
            }
#pragma unroll
            for (int o = 16; o; o >>= 1) ssum += __shfl_xor_sync(0xffffffffu, ssum, o);
            if (lane == 0) {
                float inv = 1.f / ssum;
                Bpg[h * NNODES + j] = Bj * inv;
                Dpg[h * NNODES + j] = Dj * inv;
            }
        }
    }
}

__device__ void ph_colstats(const float* __restrict__ h2,
                            float* __restrict__ mxc, float* __restrict__ invc,
                            int ltid, int wg, int grp, int ngrp, float* gsm)
{
    float* red  = gsm;
    float* red2 = gsm + 256;
    const int fl = ltid & 63, rg = ltid >> 6;
    for (int job = grp; job < IND / 64; job += ngrp) {
        const int f = job * 64 + fl;
        wgsync(wg);
        float m = -1e30f;
        for (int r0 = rg; r0 < NNODES; r0 += 4) m = fmaxf(m, h2[(size_t)r0 * IND + f]);
        red[rg * 64 + fl] = m;
        wgsync(wg);
        if (rg == 0)
            red[fl] = fmaxf(fmaxf(red[fl], red[64 + fl]), fmaxf(red[128 + fl], red[192 + fl]));
        wgsync(wg);
        const float mf = red[fl];
        float s = 0.f;
        for (int r0 = rg; r0 < NNODES; r0 += 4) s += __expf(h2[(size_t)r0 * IND + f] - mf);
        red2[rg * 64 + fl] = s;
        wgsync(wg);
        if (rg == 0) {
            float t = red2[fl] + red2[64 + fl] + red2[128 + fl] + red2[192 + fl];
            mxc[f] = mf;
            invc[f] = 1.f / t;
        }
    }
}

__device__ void ph_colsum(const float* __restrict__ r, float* __restrict__ rsum,
                          int ltid, int wg, int grp, int ngrp, float* gsm)
{
    const int cl = ltid & 31, rg = ltid >> 5;
    for (int job = grp; job < KCC / 32; job += ngrp) {
        const int c = job * 32 + cl;
        wgsync(wg);
        float s = 0.f;
        for (int r0 = rg; r0 < NNODES; r0 += 8) s += r[(size_t)r0 * KCC + c];
        gsm[rg * 32 + cl] = s;
        wgsync(wg);
        if (rg == 0) {
            float t = 0.f;
            for (int g = 0; g < 8; g++) t += gsm[g * 32 + cl];
            rsum[c] = t;
        }
    }
}

__device__ void ph_fc2(const float* __restrict__ rsum, const float* __restrict__ w,
                       const float* __restrict__ b, float* __restrict__ out)
{
    const int lane = threadIdx.x & 31;
    const int gw = blockIdx.x * (NT / 32) + (threadIdx.x >> 5);
    const int nw = gridDim.x * (NT / 32);
    for (int o = gw; o < OUTDIM; o += nw) {
        float s = 0.f;
        for (int k = lane; k < KCC; k += 32) s += rsum[k] * w[(size_t)o * KCC + k];
#pragma unroll
        for (int of = 16; of; of >>= 1) s += __shfl_xor_sync(0xffffffffu, s, of);
        if (lane == 0) out[o] = (float)NNODES * b[o] + s;
    }
}

// ----------------------------------------------------------------------------
// Persistent mega-kernel
// ----------------------------------------------------------------------------
__global__ void __launch_bounds__(NT, 1)
gat_mega(const float* __restrict__ X,  const float* __restrict__ W1,
         const float* __restrict__ a1, const float* __restrict__ W2,
         const float* __restrict__ a2, const float* __restrict__ fc1w,
         const float* __restrict__ fc1b, const float* __restrict__ fc2w,
         const float* __restrict__ fc2b, float* __restrict__ out)
{
    extern __shared__ float sm[];
    const int wg = threadIdx.x >> 8;
    const int ltid = threadIdx.x & 255;
    float* gsm = sm + wg * SMG;
    const int grp = wg * gridDim.x + blockIdx.x;
    const int ngrp = gridDim.x * NG;

    // P0: z1 partials = X @ W1^T, 128x64 tiles, K=768 split 24 (384 jobs, 2 chunks)
    ph_gemm_abt128(X, W1, g_part, HD1, IND, 32, HD1 / 64, NNODES / 128, 24,
                   ltid, wg, grp, ngrp, gsm);
    gridbar();
    // P1: combine -> z1
    ph_combine(g_z1, g_part, 24, NNODES * HD1, HD1, nullptr, 0);
    gridbar();
    // P2: layer1 scores
    ph_scores(g_z1, HD1, a1, HIDD, g_ssrc, g_sdst, NHEAD);
    gridbar();
    // P3: layer1 stats
    ph_stats(g_ssrc, g_sdst, g_Af, g_Cf, g_Bp, g_Dp, NHEAD, ltid, wg, grp, ngrp, gsm);
    gridbar();
    // P4: agg1 partials, 64x64, split 8 (256 jobs)
    ph_gemm_agg64(g_z1, g_part, g_ssrc, g_sdst, g_Af, g_Cf, g_Bp, g_Dp,
                  HD1, HIDD, 1, NNODES / 64, 8, NHEAD, 64, HD1,
                  ltid, wg, grp, ngrp, gsm);
    gridbar();
    // P5: combine + ELU -> h1
    ph_combine(g_h1, g_part, 8, NNODES * HD1, HD1, nullptr, 2);
    gridbar();
    // P6: z2 partials = h1 @ W2^T, 128x64 tiles, K=256 split 8 (384 jobs, 2 chunks)
    ph_gemm_abt128(g_h1, W2, g_part, IND, HD1, 32, IND / 64, NNODES / 128, 8,
                   ltid, wg, grp, ngrp, gsm);
    gridbar();
    // P6b: combine -> z2
    ph_combine(g_z2, g_part, 8, NNODES * IND, IND, nullptr, 0);
    gridbar();
    // P7: layer2 scores
    ph_scores(g_z2, IND, a2, IND, g_ssrc, g_sdst, 1);
    gridbar();
    // P8: layer2 stats
    ph_stats(g_ssrc, g_sdst, g_Af, g_Cf, g_Bp, g_Dp, 1, ltid, wg, grp, ngrp, gsm);
    gridbar();
    // P9: agg2 partials, 128x64 tiles, K=512 split 8 (384 jobs, 4 chunks)
    ph_gemm_agg128(g_z2, g_part, g_ssrc, g_sdst, g_Af, g_Cf, g_Bp, g_Dp,
                   IND, IND / 64, NNODES / 128, 8, 64, IND,
                   ltid, wg, grp, ngrp, gsm);
    gridbar();
    // P10: combine -> h2
    ph_combine(g_h2, g_part, 8, NNODES * IND, IND, nullptr, 0);
    gridbar();
    // P11: column softmax stats
    ph_colstats(g_h2, g_mxc, g_invc, ltid, wg, grp, ngrp, gsm);
    gridbar();
    // P12: fc1 partials = softmax(h2) @ fc1_w^T (exp fused), split 16 (384 jobs)
    ph_gemm_fc1(g_h2, g_mxc, g_invc, fc1w, g_part, ltid, wg, grp, ngrp, gsm);
    gridbar();
    // P13: combine + bias + relu -> r
    ph_combine(g_r, g_part, 16, NNODES * KCC, KCC, fc1b, 1);
    gridbar();
    // P14: column sum -> rsum
    ph_colsum(g_r, g_rsum, ltid, wg, grp, ngrp, gsm);
    gridbar();
    // P15: fc2 -> out
    ph_fc2(g_rsum, fc2w, fc2b, out);
}

// ----------------------------------------------------------------------------
// Launch
// ----------------------------------------------------------------------------
extern "C" void kernel_launch(void* const* d_in, const int* in_sizes, int n_in,
                              void* d_out, int out_size)
{
    const float* X     = (const float*)d_in[0];
    const float* W1    = (const float*)d_in[1];
    const float* a1    = (const float*)d_in[2];
    const float* W2    = (const float*)d_in[3];
    const float* a2    = (const float*)d_in[4];
    const float* fc1_w = (const float*)d_in[5];
    const float* fc1_b = (const float*)d_in[6];
    const float* fc2_w = (const float*)d_in[7];
    const float* fc2_b = (const float*)d_in[8];

    int sms = 148;
    cudaDeviceGetAttribute(&sms, cudaDevAttrMultiProcessorCount, 0);

    const size_t smbytes = (size_t)NG * SMG * sizeof(float);   // 92 KB
    cudaFuncSetAttribute(gat_mega, cudaFuncAttributeMaxDynamicSharedMemorySize,
                         (int)smbytes);

    gat_mega<<<sms, NT, smbytes>>>(X, W1, a1, W2, a2, fc1_w, fc1_b, fc2_w, fc2_b,
                                   (float*)d_out);
}

// round 11
// speedup vs baseline: 1.0713x; 1.0713x over previous
#include <cuda_runtime.h>
#include <math.h>

#define NNODES 512
#define IND    768
#define HIDD   64
#define NHEAD  4
#define HD1    256
#define KCC    192
#define OUTDIM 256
#define NT     768
#define NG     3
#define GSZ    256
#define SMG    5184         // smem floats per warpgroup
#define RS     20           // smem row stride (16 k + 4 pad)
#define JOBSLOT 5120        // per-group smem job ticket slot

// ----------------------------------------------------------------------------
// Device scratch
// ----------------------------------------------------------------------------
__device__ float g_z1[NNODES * HD1];
__device__ float g_h1[NNODES * HD1];
__device__ float g_z2[NNODES * IND];
__device__ float g_h2[NNODES * IND];
__device__ float g_r [NNODES * KCC];
__device__ float g_part[4 * NNODES * IND];
__device__ float g_ssrc[NHEAD * NNODES], g_sdst[NHEAD * NNODES];
__device__ float g_Af[NHEAD * NNODES], g_Cf[NHEAD * NNODES];
__device__ float g_Bp[NHEAD * NNODES], g_Dp[NHEAD * NNODES];
__device__ float g_mxc[IND], g_invc[IND];
__device__ float g_rsum[KCC];
__device__ unsigned g_tick[8];
__device__ unsigned g_cnt8[8];
__device__ unsigned g_root = 0;
__device__ volatile unsigned g_bargen = 0;

// ----------------------------------------------------------------------------
// Barriers + cp.async helpers
// ----------------------------------------------------------------------------
__device__ __forceinline__ void wgsync(int wg) {
    asm volatile("bar.sync %0, %1;" :: "r"(wg + 1), "n"(GSZ) : "memory");
}

__device__ __forceinline__ void gridbar() {
    __syncthreads();
    if (threadIdx.x == 0) {
        __threadfence();
        const unsigned gen = g_bargen;
        const unsigned b = blockIdx.x & 7u;
        const unsigned bsz = (gridDim.x >> 3) + (((gridDim.x & 7u) > b) ? 1u : 0u);
        if (atomicAdd(&g_cnt8[b], 1u) == bsz - 1u) {
            atomicExch(&g_cnt8[b], 0u);
            __threadfence();
            if (atomicAdd(&g_root, 1u) == 7u) {
                atomicExch(&g_root, 0u);
                __threadfence();
                atomicAdd((unsigned*)&g_bargen, 1u);
            }
        }
        while (g_bargen == gen) { __nanosleep(32); }
        __threadfence();
    }
    __syncthreads();
}

__device__ __forceinline__ unsigned su32(const void* p) {
    return (unsigned)__cvta_generic_to_shared(p);
}
__device__ __forceinline__ void cpa16(unsigned d, const void* s) {
    asm volatile("cp.async.cg.shared.global [%0], [%1], 16;" :: "r"(d), "l"(s));
}
__device__ __forceinline__ void cpcommit() { asm volatile("cp.async.commit_group;"); }
__device__ __forceinline__ void cpwait0()  { asm volatile("cp.async.wait_group 0;"); }

// steal one job for the warpgroup; returns -1 when exhausted
__device__ __forceinline__ int steal(unsigned* tick, int njobs, int ltid, int wg,
                                     float* gsm)
{
    volatile unsigned* slot = (volatile unsigned*)(gsm + JOBSLOT);
    if (ltid == 0) *slot = atomicAdd(tick, 1u);
    wgsync(wg);
    int job = (int)*slot;
    return (job < njobs) ? job : -1;
}

// ----------------------------------------------------------------------------
// Pipelined SGEMM 64x64, 4x4/thread, chunk=16, one barrier/chunk, stealing.
// Cpart[z][512,Ncols] = A[512,K_ld] @ B[Ncols,K_ld]^T over k-split z.
// ----------------------------------------------------------------------------
__device__ void ph_gemm_abt(const float* __restrict__ A, const float* __restrict__ B,
                            float* __restrict__ C, int Ncols, int K_ld, int klen,
                            int gx, int gy, int nsplit, unsigned* tick,
                            int ltid, int wg, float* gsm)
{
    float* As = gsm;                 // 2 * 1280
    float* Bs = gsm + 2560;          // 2 * 1280
    const int tx = ltid & 15, ty = ltid >> 4;
    const int isB  = ltid >> 7;
    const int lrow = (ltid & 127) >> 1;
    const int lh   = ltid & 1;
    const int njobs = gx * gy * nsplit;
    const int nch = klen >> 4;

    for (;;) {
        const int job = steal(tick, njobs, ltid, wg, gsm);   // wgsync inside
        if (job < 0) break;
        const int z = job / (gx * gy);
        const int rem = job % (gx * gy);
        const int by = rem / gx, bx = rem % gx;
        const int m0 = by * 64, n0 = bx * 64, kstart = z * klen;

        const float* src0 = isB ? (B + (size_t)(n0 + lrow) * K_ld + kstart + lh * 8)
                                : (A + (size_t)(m0 + lrow) * K_ld + kstart + lh * 8);
        const unsigned dst0 = isB ? su32(&Bs[lrow * RS + lh * 8])
                                  : su32(&As[lrow * RS + lh * 8]);

        float acc[4][4];
#pragma unroll
        for (int i = 0; i < 4; i++)
#pragma unroll
            for (int j = 0; j < 4; j++) acc[i][j] = 0.f;

        cpa16(dst0, src0);
        cpa16(dst0 + 16, src0 + 4);
        cpcommit();

        for (int c = 0; c < nch; c++) {
            const int cb = c & 1;
            cpwait0();
            wgsync(wg);
            if (c + 1 < nch) {
                const unsigned d = dst0 + (cb ^ 1) * 5120;
                const float* s = src0 + (c + 1) * 16;
                cpa16(d, s);
                cpa16(d + 16, s + 4);
                cpcommit();
            }
            const float* Ab = As + cb * 1280;
            const float* Bb = Bs + cb * 1280;
#pragma unroll
            for (int q = 0; q < 4; q++) {
                float4 af[4], bf[4];
#pragma unroll
                for (int i = 0; i < 4; i++)
                    af[i] = *(const float4*)&Ab[(ty + 16 * i) * RS + q * 4];
#pragma unroll
                for (int j = 0; j < 4; j++)
                    bf[j] = *(const float4*)&Bb[(tx + 16 * j) * RS + q * 4];
#pragma unroll
                for (int i = 0; i < 4; i++)
#pragma unroll
                    for (int j = 0; j < 4; j++) {
                        acc[i][j] += af[i].x * bf[j].x;
                        acc[i][j] += af[i].y * bf[j].y;
                        acc[i][j] += af[i].z * bf[j].z;
                        acc[i][j] += af[i].w * bf[j].w;
                    }
            }
        }
        wgsync(wg);     // all done with smem before next steal overwrites

        float* outp = C + (size_t)z * NNODES * Ncols;
#pragma unroll
        for (int i = 0; i < 4; i++)
#pragma unroll
            for (int j = 0; j < 4; j++)
                outp[(size_t)(m0 + ty + 16 * i) * Ncols + n0 + tx + 16 * j] = acc[i][j];
    }
}

// ----------------------------------------------------------------------------
// Pipelined aggregation GEMM 64x64, stealing. alpha built on the fly.
// ----------------------------------------------------------------------------
__device__ void ph_gemm_agg(const float* __restrict__ Z, float* __restrict__ C,
                            const float* __restrict__ ssrc, const float* __restrict__ sdst,
                            const float* __restrict__ Af, const float* __restrict__ Cf,
                            const float* __restrict__ Bp, const float* __restrict__ Dp,
                            int ldz, int hd, int gx, int gy, int nsplit, int H,
                            int klen, int ldc, unsigned* tick,
                            int ltid, int wg, float* gsm)
{
    float* Asb = gsm;              // 2 * 1088
    float* Zs  = gsm + 2176;       // 2 * 1088
    float* Ex  = gsm + 4352;       // 192
    const int tx = ltid & 15, ty = ltid >> 4;
    const int zrow = ltid >> 4, zf4 = ltid & 15;
    const int ail = ltid >> 4, aj4 = (ltid & 15) * 4;
    const int jobs_per_h = gx * gy * nsplit;
    const int njobs = H * jobs_per_h;
    const int nch = klen >> 4;

    for (;;) {
        const int job = steal(tick, njobs, ltid, wg, gsm);
        if (job < 0) break;
        const int h = job / jobs_per_h;
        int rem = job % jobs_per_h;
        const int z = rem / (gx * gy); rem %= gx * gy;
        const int by = rem / gx, bx = rem % gx;
        const int m0 = by * 64, ncol0 = h * hd + bx * 64, kstart = z * klen;
        const float* ss = ssrc + h * NNODES;
        const float* af = Af + h * NNODES;
        const float* cf = Cf + h * NNODES;

        auto build = [&](int cc, float* dst) {
            int ig = kstart + cc * 16 + ail;
            float ssv = ss[ig], afv = af[ig], cfv = cf[ig];
            int jj = aj4;
            float4 w;
            float x0 = ssv + Ex[jj + 0];
            float x1 = ssv + Ex[jj + 1];
            float x2 = ssv + Ex[jj + 2];
            float x3 = ssv + Ex[jj + 3];
            w.x = x0 > 0.f ? afv * Ex[64 + jj + 0] : cfv * Ex[128 + jj + 0];
            w.y = x1 > 0.f ? afv * Ex[64 + jj + 1] : cfv * Ex[128 + jj + 1];
            w.z = x2 > 0.f ? afv * Ex[64 + jj + 2] : cfv * Ex[128 + jj + 2];
            w.w = x3 > 0.f ? afv * Ex[64 + jj + 3] : cfv * Ex[128 + jj + 3];
            if (ig == m0 + jj + 0) w.x = 0.f;
            if (ig == m0 + jj + 1) w.y = 0.f;
            if (ig == m0 + jj + 2) w.z = 0.f;
            if (ig == m0 + jj + 3) w.w = 0.f;
            *(float4*)&dst[ail * 68 + aj4] = w;
        };

        if (ltid < 64) {
            int j = m0 + ltid;
            Ex[ltid]       = sdst[h * NNODES + j];
            Ex[64 + ltid]  = Bp[h * NNODES + j];
            Ex[128 + ltid] = Dp[h * NNODES + j];
        }
        wgsync(wg);                         // Ex visible to ALL threads

        build(0, Asb);
        const float* srcZ = Z + (size_t)(kstart + zrow) * ldz + ncol0 + zf4 * 4;
        const unsigned dstZ = su32(&Zs[zrow * 68 + zf4 * 4]);
        cpa16(dstZ, srcZ);
        cpcommit();

        float acc[4][4];
#pragma unroll
        for (int i = 0; i < 4; i++)
#pragma unroll
            for (int j = 0; j < 4; j++) acc[i][j] = 0.f;

        for (int c = 0; c < nch; c++) {
            const int cb = c & 1;
            cpwait0();
            wgsync(wg);
            if (c + 1 < nch) {
                cpa16(dstZ + (cb ^ 1) * 4352, srcZ + (size_t)(c + 1) * 16 * ldz);
                cpcommit();
                build(c + 1, Asb + (cb ^ 1) * 1088);
            }
            const float* Ab = Asb + cb * 1088;
            const float* Zb = Zs  + cb * 1088;
#pragma unroll
            for (int kk = 0; kk < 16; kk++) {
                float4 a = *(const float4*)&Ab[kk * 68 + ty * 4];
                float4 b = *(const float4*)&Zb[kk * 68 + tx * 4];
                float a4[4] = {a.x, a.y, a.z, a.w};
                float b4[4] = {b.x, b.y, b.z, b.w};
#pragma unroll
                for (int i = 0; i < 4; i++)
#pragma unroll
                    for (int j = 0; j < 4; j++) acc[i][j] += a4[i] * b4[j];
            }
        }
        wgsync(wg);

        float* outp = C + (size_t)z * NNODES * ldc;
#pragma unroll
        for (int i = 0; i < 4; i++)
#pragma unroll
            for (int j = 0; j < 4; j++)
                outp[(size_t)(m0 + ty * 4 + i) * ldc + ncol0 + tx * 4 + j] = acc[i][j];
    }
}

// ----------------------------------------------------------------------------
// fc1 GEMM with softmax folded into A build, stealing (384 jobs, klen 48)
// ----------------------------------------------------------------------------
__device__ void ph_gemm_fc1(const float* __restrict__ h2m, const float* __restrict__ mxc,
                            const float* __restrict__ invc, const float* __restrict__ Bw,
                            float* __restrict__ C, unsigned* tick,
                            int ltid, int wg, float* gsm)
{
    float* As = gsm;
    float* Bs = gsm + 2560;
    const int tx = ltid & 15, ty = ltid >> 4;
    const int row = ltid >> 2, kq = (ltid & 3) * 4;
    const int njobs = 384;
    const int nch = 3;

    for (;;) {
        const int job = steal(tick, njobs, ltid, wg, gsm);
        if (job < 0) break;
        const int z = job / 24;
        const int rem = job % 24;
        const int by = rem / 3, bx = rem % 3;
        const int m0 = by * 64, n0 = bx * 64, kstart = z * 48;

        const unsigned dstB = su32(&Bs[row * RS + kq]);
        const float* srcB = Bw + (size_t)(n0 + row) * IND + kstart + kq;
        const float* srcA = h2m + (size_t)(m0 + row) * IND + kstart + kq;

        float acc[4][4];
#pragma unroll
        for (int i = 0; i < 4; i++)
#pragma unroll
            for (int j = 0; j < 4; j++) acc[i][j] = 0.f;

        cpa16(dstB, srcB);
        cpcommit();
        {
            float4 raw = *(const float4*)srcA;
            float4 mx  = *(const float4*)&mxc[kstart + kq];
            float4 iv  = *(const float4*)&invc[kstart + kq];
            float4 v;
            v.x = __expf(raw.x - mx.x) * iv.x;
            v.y = __expf(raw.y - mx.y) * iv.y;
            v.z = __expf(raw.z - mx.z) * iv.z;
            v.w = __expf(raw.w - mx.w) * iv.w;
            *(float4*)&As[row * RS + kq] = v;
        }

        for (int c = 0; c < nch; c++) {
            const int cb = c & 1;
            cpwait0();
            wgsync(wg);
            float4 raw;
            const bool pre = (c + 1 < nch);
            if (pre) {
                cpa16(dstB + (cb ^ 1) * 5120u, srcB + (c + 1) * 16);
                cpcommit();
                raw = *(const float4*)(srcA + (c + 1) * 16);
            }
            const float* Ab = As + cb * 1280;
            const float* Bb = Bs + cb * 1280;
#pragma unroll
            for (int q = 0; q < 4; q++) {
                float4 af[4], bf[4];
#pragma unroll
                for (int i = 0; i < 4; i++)
                    af[i] = *(const float4*)&Ab[(ty + 16 * i) * RS + q * 4];
#pragma unroll
                for (int j = 0; j < 4; j++)
                    bf[j] = *(const float4*)&Bb[(tx + 16 * j) * RS + q * 4];
#pragma unroll
                for (int i = 0; i < 4; i++)
#pragma unroll
                    for (int j = 0; j < 4; j++) {
                        acc[i][j] += af[i].x * bf[j].x;
                        acc[i][j] += af[i].y * bf[j].y;
                        acc[i][j] += af[i].z * bf[j].z;
                        acc[i][j] += af[i].w * bf[j].w;
                    }
            }
            if (pre) {
                const int kg = kstart + (c + 1) * 16 + kq;
                float4 mx = *(const float4*)&mxc[kg];
                float4 iv = *(const float4*)&invc[kg];
                float4 v;
                v.x = __expf(raw.x - mx.x) * iv.x;
                v.y = __expf(raw.y - mx.y) * iv.y;
                v.z = __expf(raw.z - mx.z) * iv.z;
                v.w = __expf(raw.w - mx.w) * iv.w;
                *(float4*)&As[(cb ^ 1) * 1280 + row * RS + kq] = v;
            }
        }
        wgsync(wg);

        float* outp = C + (size_t)z * NNODES * KCC;
#pragma unroll
        for (int i = 0; i < 4; i++)
#pragma unroll
            for (int j = 0; j < 4; j++)
                outp[(size_t)(m0 + ty + 16 * i) * KCC + n0 + tx + 16 * j] = acc[i][j];
    }
}

// ----------------------------------------------------------------------------
// Fused combine + layer1 scores. Block (768 thr) = 3 rows of z1 per iteration.
// ----------------------------------------------------------------------------
__device__ void ph_combine_scores1(const float* __restrict__ part, int nparts,
                                   const float* __restrict__ a1,
                                   float* __restrict__ z1,
                                   float* __restrict__ ssrc, float* __restrict__ sdst,
                                   float* smblk)
{
    const int tid = threadIdx.x;
    const int total = NNODES * HD1;
    const int d = tid & 255, h = d >> 6, l = d & 63;
    const float a_s = a1[h * 128 + l];
    const float a_d = a1[h * 128 + 64 + l];

    for (int base = blockIdx.x * NT; base < total; base += gridDim.x * NT) {
        const int idx = base + tid;
        float v = 0.f;
        if (idx < total) {
            for (int p = 0; p < nparts; p++) v += part[(size_t)p * total + idx];
            z1[idx] = v;
        }
        float s1 = v * a_s, s2 = v * a_d;
#pragma unroll
        for (int o = 16; o; o >>= 1) {
            s1 += __shfl_xor_sync(0xffffffffu, s1, o);
            s2 += __shfl_xor_sync(0xffffffffu, s2, o);
        }
        const int w = tid >> 5;
        if ((tid & 31) == 0) { smblk[w] = s1; smblk[24 + w] = s2; }
        __syncthreads();
        if (tid < 12) {
            float t1 = smblk[2 * tid] + smblk[2 * tid + 1];
            float t2 = smblk[24 + 2 * tid] + smblk[24 + 2 * tid + 1];
            int row = (base >> 8) + (tid >> 2);
            int hh = tid & 3;
            if (row < NNODES) {
                ssrc[hh * NNODES + row] = t1;
                sdst[hh * NNODES + row] = t2;
            }
        }
        __syncthreads();
    }
}

// ----------------------------------------------------------------------------
// Fused combine + layer2 scores. Block = exactly 1 row of z2 per iteration.
// ----------------------------------------------------------------------------
__device__ void ph_combine_scores2(const float* __restrict__ part, int nparts,
                                   const float* __restrict__ a2,
                                   float* __restrict__ z2,
                                   float* __restrict__ ssrc, float* __restrict__ sdst,
                                   float* smblk)
{
    const int tid = threadIdx.x;
    const int total = NNODES * IND;
    const float a_s = a2[tid];
    const float a_d = a2[IND + tid];

    for (int base = blockIdx.x * NT; base < total; base += gridDim.x * NT) {
        const int idx = base + tid;
        float v = 0.f;
        for (int p = 0; p < nparts; p++) v += part[(size_t)p * total + idx];
        z2[idx] = v;
        float s1 = v * a_s, s2 = v * a_d;
#pragma unroll
        for (int o = 16; o; o >>= 1) {
            s1 += __shfl_xor_sync(0xffffffffu, s1, o);
            s2 += __shfl_xor_sync(0xffffffffu, s2, o);
        }
        const int w = tid >> 5;
        if ((tid & 31) == 0) { smblk[w] = s1; smblk[24 + w] = s2; }
        __syncthreads();
        if (tid == 0) {
            float t1 = 0.f, t2 = 0.f;
            for (int q = 0; q < 24; q++) { t1 += smblk[q]; t2 += smblk[24 + q]; }
            const int row = base / IND;
            ssrc[row] = t1;
            sdst[row] = t2;
        }
        __syncthreads();
    }
}

// ----------------------------------------------------------------------------
// Fused fc1 combine + bias + relu + column-sum (atomic). Block = 4 rows of r.
// ----------------------------------------------------------------------------
__device__ void ph_combine_relu_colsum(const float* __restrict__ part, int nparts,
                                       const float* __restrict__ bias,
                                       float* __restrict__ r, float* smblk)
{
    const int tid = threadIdx.x;
    const int total = NNODES * KCC;      // 98304 = 128 blocks exactly
    const float b = bias[tid % KCC];

    for (int base = blockIdx.x * NT; base < total; base += gridDim.x * NT) {
        const int idx = base + tid;
        float v = 0.f;
        for (int p = 0; p < nparts; p++) v += part[(size_t)p * total + idx];
        v = fmaxf(v + b, 0.f);
        r[idx] = v;
        smblk[tid] = v;
        __syncthreads();
        if (tid < KCC)
            atomicAdd(&g_rsum[tid],
                      smblk[tid] + smblk[tid + KCC] + smblk[tid + 2 * KCC] +
                      smblk[tid + 3 * KCC]);
        __syncthreads();
    }
}

// ----------------------------------------------------------------------------
// Plain combine (ELU / none)
// ----------------------------------------------------------------------------
__device__ void ph_combine(float* __restrict__ out, const float* __restrict__ part,
                           int nparts, int total, int act)
{
    for (int idx = blockIdx.x * NT + threadIdx.x; idx < total; idx += gridDim.x * NT) {
        float s = 0.f;
        for (int p = 0; p < nparts; p++) s += part[(size_t)p * total + idx];
        if (act == 2) s = s > 0.f ? s : expm1f(s);
        out[idx] = s;
    }
}

// ----------------------------------------------------------------------------
// Separable-softmax stats (static mapping; 32 / 8 jobs)
// ----------------------------------------------------------------------------
__device__ void ph_stats(const float* __restrict__ ssrc, const float* __restrict__ sdst,
                         float* __restrict__ Af, float* __restrict__ Cf,
                         float* __restrict__ Bpg, float* __restrict__ Dpg,
                         int H, int ltid, int wg, int grp, int ngrp, float* gsm)
{
    float* ss  = gsm;
    float* aa  = gsm + 512;
    float* cc  = gsm + 1024;
    float* rm1 = gsm + 1536;
    float* rm2 = gsm + 1792;
    int*   ri1 = (int*)(gsm + 2048);
    const int cpj = NNODES / 64;
    const int njobs = H * cpj;

    for (int job = grp; job < njobs; job += ngrp) {
        const int h = job / cpj, jc = job % cpj;
        wgsync(wg);
        for (int i = ltid; i < NNODES; i += GSZ) ss[i] = ssrc[h * NNODES + i];
        wgsync(wg);

        float m1 = -1e30f, m2 = -1e30f; int i1 = -1;
        for (int i = ltid; i < NNODES; i += GSZ) {
            float v = ss[i];
            if (v > m1) { m2 = m1; m1 = v; i1 = i; }
            else if (v > m2) m2 = v;
        }
        rm1[ltid] = m1; rm2[ltid] = m2; ri1[ltid] = i1;
        wgsync(wg);
        if (ltid < 32) {
            float a1 = rm1[ltid], a2 = rm2[ltid]; int ai = ri1[ltid];
            for (int t = ltid + 32; t < GSZ; t += 32) {
                float b1 = rm1[t], b2 = rm2[t];
                if (b1 > a1) { a2 = fmaxf(a1, b2); a1 = b1; ai = ri1[t]; }
                else         { a2 = fmaxf(a2, b1); }
            }
            rm1[ltid] = a1; rm2[ltid] = a2; ri1[ltid] = ai;
        }
        wgsync(wg);
        if (ltid == 0) {
            float a1 = rm1[0], a2 = rm2[0]; int ai = ri1[0];
            for (int t = 1; t < 32; t++) {
                float b1 = rm1[t], b2 = rm2[t];
                if (b1 > a1) { a2 = fmaxf(a1, b2); a1 = b1; ai = ri1[t]; }
                else         { a2 = fmaxf(a2, b1); }
            }
            rm1[0] = a1; rm2[0] = a2; ri1[0] = ai;
        }
        wgsync(wg);
        const float Ms = rm1[0], M2 = rm2[0];
        const int iarg = ri1[0];

        for (int i = ltid; i < NNODES; i += GSZ) {
            float dd = ss[i] - Ms;
            aa[i] = __expf(dd);
            cc[i] = __expf(0.01f * dd);
        }
        wgsync(wg);
        if (jc == 0) {
            for (int i = ltid; i < NNODES; i += GSZ) {
                Af[h * NNODES + i] = aa[i];
                Cf[h * NNODES + i] = cc[i];
            }
        }

        const int wid = ltid >> 5, lane = ltid & 31;
        for (int jj = wid; jj < 64; jj += 8) {
            int j = jc * 64 + jj;
            float sd = sdst[h * NNODES + j];
            float smx = (j == iarg) ? M2 : Ms;
            float t0 = smx + sd;
            float mxj = t0 > 0.f ? t0 : 0.01f * t0;
            float Bj = __expf(Ms + sd - mxj);
            float Dj = __expf(0.01f * (Ms + sd) - mxj);
            float ssum = 0.f;
            for (int i = lane; i < NNODES; i += 32) {
                if (i == j) continue;
                float x = ss[i] + sd;
                ssum += (x > 0.f) ? aa[i] * Bj : cc[i] * Dj;
            }
#pragma unroll
            for (int o = 16; o; o >>= 1) ssum += __shfl_xor_sync(0xffffffffu, ssum, o);
            if (lane == 0) {
                float inv = 1.f / ssum;
                Bpg[h * NNODES + j] = Bj * inv;
                Dpg[h * NNODES + j] = Dj * inv;
            }
        }
    }
}

// ----------------------------------------------------------------------------
// Column softmax stats
// ----------------------------------------------------------------------------
__device__ void ph_colstats(const float* __restrict__ h2,
                            float* __restrict__ mxc, float* __restrict__ invc,
                            int ltid, int wg, int grp, int ngrp, float* gsm)
{
    float* red  = gsm;
    float* red2 = gsm + 256;
    const int fl = ltid & 63, rg = ltid >> 6;
    for (int job = grp; job < IND / 64; job += ngrp) {
        const int f = job * 64 + fl;
        wgsync(wg);
        float m = -1e30f;
        for (int r0 = rg; r0 < NNODES; r0 += 4) m = fmaxf(m, h2[(size_t)r0 * IND + f]);
        red[rg * 64 + fl] = m;
        wgsync(wg);
        if (rg == 0)
            red[fl] = fmaxf(fmaxf(red[fl], red[64 + fl]), fmaxf(red[128 + fl], red[192 + fl]));
        wgsync(wg);
        const float mf = red[fl];
        float s = 0.f;
        for (int r0 = rg; r0 < NNODES; r0 += 4) s += __expf(h2[(size_t)r0 * IND + f] - mf);
        red2[rg * 64 + fl] = s;
        wgsync(wg);
        if (rg == 0) {
            float t = red2[fl] + red2[64 + fl] + red2[128 + fl] + red2[192 + fl];
            mxc[f] = mf;
            invc[f] = 1.f / t;
        }
    }
}

// ----------------------------------------------------------------------------
// fc2: warp per output
// ----------------------------------------------------------------------------
__device__ void ph_fc2(const float* __restrict__ rsum, const float* __restrict__ w,
                       const float* __restrict__ b, float* __restrict__ out)
{
    const int lane = threadIdx.x & 31;
    const int gw = blockIdx.x * (NT / 32) + (threadIdx.x >> 5);
    const int nw = gridDim.x * (NT / 32);
    for (int o = gw; o < OUTDIM; o += nw) {
        float s = 0.f;
        for (int k = lane; k < KCC; k += 32) s += rsum[k] * w[(size_t)o * KCC + k];
#pragma unroll
        for (int of = 16; of; of >>= 1) s += __shfl_xor_sync(0xffffffffu, s, of);
        if (lane == 0) out[o] = (float)NNODES * b[o] + s;
    }
}

// ----------------------------------------------------------------------------
// Persistent mega-kernel
// ----------------------------------------------------------------------------
__global__ void __launch_bounds__(NT, 1)
gat_mega(const float* __restrict__ X,  const float* __restrict__ W1,
         const float* __restrict__ a1, const float* __restrict__ W2,
         const float* __restrict__ a2, const float* __restrict__ fc1w,
         const float* __restrict__ fc1b, const float* __restrict__ fc2w,
         const float* __restrict__ fc2b, float* __restrict__ out)
{
    extern __shared__ float sm[];
    const int wg = threadIdx.x >> 8;
    const int ltid = threadIdx.x & 255;
    float* gsm = sm + wg * SMG;
    const int grp = wg * gridDim.x + blockIdx.x;
    const int ngrp = gridDim.x * NG;

    // INIT: reset tickets + rsum
    if (blockIdx.x == 0) {
        if (threadIdx.x < 8) g_tick[threadIdx.x] = 0;
        if (threadIdx.x >= 32 && threadIdx.x < 32 + KCC) g_rsum[threadIdx.x - 32] = 0.f;
    }
    gridbar();
    // P0: z1 partials = X @ W1^T, split 12 (384 jobs)
    ph_gemm_abt(X, W1, g_part, HD1, IND, 64, HD1 / 64, NNODES / 64, 12,
                &g_tick[0], ltid, wg, gsm);
    gridbar();
    // P1: combine -> z1 + layer1 scores (fused)
    ph_combine_scores1(g_part, 12, a1, g_z1, g_ssrc, g_sdst, sm);
    gridbar();
    // P2: layer1 stats
    ph_stats(g_ssrc, g_sdst, g_Af, g_Cf, g_Bp, g_Dp, NHEAD, ltid, wg, grp, ngrp, gsm);
    gridbar();
    // P3: agg1 partials, split 8 (256 jobs)
    ph_gemm_agg(g_z1, g_part, g_ssrc, g_sdst, g_Af, g_Cf, g_Bp, g_Dp,
                HD1, HIDD, 1, NNODES / 64, 8, NHEAD, 64, HD1,
                &g_tick[1], ltid, wg, gsm);
    gridbar();
    // P4: combine + ELU -> h1
    ph_combine(g_h1, g_part, 8, NNODES * HD1, 2);
    gridbar();
    // P5: z2 partials = h1 @ W2^T, split 4 (384 jobs)
    ph_gemm_abt(g_h1, W2, g_part, IND, HD1, 64, IND / 64, NNODES / 64, 4,
                &g_tick[2], ltid, wg, gsm);
    gridbar();
    // P6: combine -> z2 + layer2 scores (fused)
    ph_combine_scores2(g_part, 4, a2, g_z2, g_ssrc, g_sdst, sm);
    gridbar();
    // P7: layer2 stats
    ph_stats(g_ssrc, g_sdst, g_Af, g_Cf, g_Bp, g_Dp, 1, ltid, wg, grp, ngrp, gsm);
    gridbar();
    // P8: agg2 partials, split 4 (384 jobs, klen 128)
    ph_gemm_agg(g_z2, g_part, g_ssrc, g_sdst, g_Af, g_Cf, g_Bp, g_Dp,
                IND, 0, IND / 64, NNODES / 64, 4, 1, 128, IND,
                &g_tick[3], ltid, wg, gsm);
    gridbar();
    // P9: combine -> h2
    ph_combine(g_h2, g_part, 4, NNODES * IND, 0);
    gridbar();
    // P10: column softmax stats
    ph_colstats(g_h2, g_mxc, g_invc, ltid, wg, grp, ngrp, gsm);
    gridbar();
    // P11: fc1 partials = softmax(h2) @ fc1_w^T (exp fused), 384 jobs
    ph_gemm_fc1(g_h2, g_mxc, g_invc, fc1w, g_part, &g_tick[4], ltid, wg, gsm);
    gridbar();
    // P12: combine + bias + relu -> r, + atomic column sum (fused)
    ph_combine_relu_colsum(g_part, 16, fc1b, g_r, sm);
    gridbar();
    // P13: fc2 -> out
    ph_fc2(g_rsum, fc2w, fc2b, out);
}

// ----------------------------------------------------------------------------
// Launch
// ----------------------------------------------------------------------------
extern "C" void kernel_launch(void* const* d_in, const int* in_sizes, int n_in,
                              void* d_out, int out_size)
{
    const float* X     = (const float*)d_in[0];
    const float* W1    = (const float*)d_in[1];
    const float* a1    = (const float*)d_in[2];
    const float* W2    = (const float*)d_in[3];
    const float* a2    = (const float*)d_in[4];
    const float* fc1_w = (const float*)d_in[5];
    const float* fc1_b = (const float*)d_in[6];
    const float* fc2_w = (const float*)d_in[7];
    const float* fc2_b = (const float*)d_in[8];

    int sms = 148;
    cudaDeviceGetAttribute(&sms, cudaDevAttrMultiProcessorCount, 0);

    const size_t smbytes = (size_t)NG * SMG * sizeof(float);   // ~61 KB
    cudaFuncSetAttribute(gat_mega, cudaFuncAttributeMaxDynamicSharedMemorySize,
                         (int)smbytes);

    gat_mega<<<sms, NT, smbytes>>>(X, W1, a1, W2, a2, fc1_w, fc1_b, fc2_w, fc2_b,
                                   (float*)d_out);
}